// round 1
// baseline (speedup 1.0000x reference)
#include <cuda_runtime.h>
#include <math.h>

#define NT 4
#define PT 8192
#define NH 32
#define NU 128
#define NPTS 32768

// ---------------- scratch (device globals; no allocations) ----------------
__device__ float g_KT[NT * NU * NU];   // k_w transposed per type
__device__ float g_QK[NT * NU * NU];   // q_w @ k_w^T      (so qk = x @ QK)
__device__ float g_VF[NT * NU * NU];   // v_w @ fc_w       (folded, relu is after fc)
__device__ float g_Q[(size_t)NT * PT * NU];   // 16 MB: per-entity q vectors
__device__ float g_RAW[(size_t)NT * PT * NH]; // 4 MB: raw attention scores
__device__ float g_M[NT * NH];
__device__ float g_S[NT * NH];

// ---------------- K0a: transpose k_w per type ----------------
__global__ void __launch_bounds__(256) ktrans(const float* __restrict__ kw) {
    __shared__ float tile[32][33];
    int t = blockIdx.z;
    int bx = blockIdx.x * 32, by = blockIdx.y * 32;
    const float* src = kw + (size_t)t * NU * NU;
    float* dst = g_KT + (size_t)t * NU * NU;
    int tx = threadIdx.x, ty = threadIdx.y;
#pragma unroll
    for (int i = 0; i < 32; i += 8)
        tile[ty + i][tx] = src[(by + ty + i) * NU + bx + tx];
    __syncthreads();
#pragma unroll
    for (int i = 0; i < 32; i += 8)
        dst[(bx + ty + i) * NU + by + tx] = tile[tx][ty + i];
}

// ---------------- K0b: QK[t][e][u] = sum_v q_w[t][e][v] * k_w[t][u][v] ----------------
__global__ void __launch_bounds__(128) kqk(const float* __restrict__ qw) {
    int t = blockIdx.y, e = blockIdx.x, u = threadIdx.x;
    const float* q = qw + ((size_t)t * NU + e) * NU;
    const float* kt = g_KT + (size_t)t * NU * NU;
    float acc = 0.f;
#pragma unroll 8
    for (int v = 0; v < NU; ++v)
        acc = fmaf(q[v], kt[v * NU + u], acc);   // q[v] uniform, kt coalesced
    g_QK[((size_t)t * NU + e) * NU + u] = acc;
}

// ---------------- K0c: VF[t][w][j] = sum_u v_w[t][w][u] * fc_w[t][u][j] ----------------
__global__ void __launch_bounds__(128) kvf(const float* __restrict__ vw,
                                           const float* __restrict__ fw) {
    int t = blockIdx.y, w = blockIdx.x, j = threadIdx.x;
    const float* vr = vw + ((size_t)t * NU + w) * NU;
    const float* f = fw + (size_t)t * NU * NU;
    float acc = 0.f;
#pragma unroll 8
    for (int u = 0; u < NU; ++u)
        acc = fmaf(vr[u], f[u * NU + j], acc);   // vr[u] uniform, f coalesced
    g_VF[((size_t)t * NU + w) * NU + j] = acc;
}

// ---------------- K1: per entity: q = x@q_w, qk = x@QK, raw[h] = hist[h]·qk ----------------
// One warp per entity, 4 entities per 128-thread block. float4 weight loads (4 FMA / lane-load).
__global__ void __launch_bounds__(128) k1(const float* __restrict__ state,
                                          const float* __restrict__ hist,
                                          const int* __restrict__ eidx,
                                          const float* __restrict__ qw) {
    __shared__ float sx[4][NU];
    __shared__ float sqk[4][NU];
    int lane = threadIdx.x & 31;
    int warp = threadIdx.x >> 5;
    int t = blockIdx.y;
    int n = blockIdx.x * 4 + warp;
    int idx = eidx[t * PT + n];

    // gather x (512B coalesced per warp)
    float4 x4 = __ldcs((const float4*)(state + (size_t)idx * NU) + lane);
    ((float4*)sx[warp])[lane] = x4;
    __syncwarp();

    const float4* qw4 = (const float4*)(qw + (size_t)t * NU * NU);
    const float4* qk4 = (const float4*)(g_QK + (size_t)t * NU * NU);
    float4 qa = make_float4(0.f, 0.f, 0.f, 0.f);
    float4 ka = make_float4(0.f, 0.f, 0.f, 0.f);
#pragma unroll 4
    for (int v = 0; v < NU; ++v) {
        float xv = sx[warp][v];
        float4 wq = qw4[v * 32 + lane];
        float4 wk = qk4[v * 32 + lane];
        qa.x = fmaf(xv, wq.x, qa.x); qa.y = fmaf(xv, wq.y, qa.y);
        qa.z = fmaf(xv, wq.z, qa.z); qa.w = fmaf(xv, wq.w, qa.w);
        ka.x = fmaf(xv, wk.x, ka.x); ka.y = fmaf(xv, wk.y, ka.y);
        ka.z = fmaf(xv, wk.z, ka.z); ka.w = fmaf(xv, wk.w, ka.w);
    }
    ((float4*)(g_Q + ((size_t)t * PT + n) * NU))[lane] = qa;
    ((float4*)sqk[warp])[lane] = ka;
    __syncwarp();

    float4 qkl = ((const float4*)sqk[warp])[lane];
    const float4* h4 = (const float4*)(hist + (size_t)idx * NH * NU);
    float myraw = 0.f;
#pragma unroll 8
    for (int h = 0; h < NH; ++h) {
        float4 r4 = __ldcs(h4 + h * 32 + lane);   // 512B row, evict-first
        float p = fmaf(r4.x, qkl.x, fmaf(r4.y, qkl.y, fmaf(r4.z, qkl.z, r4.w * qkl.w)));
#pragma unroll
        for (int o = 16; o; o >>= 1) p += __shfl_xor_sync(0xffffffffu, p, o);
        if (lane == h) myraw = p;
    }
    g_RAW[((size_t)t * PT + n) * NH + lane] = myraw;  // one coalesced 128B store per warp
}

// ---------------- K2: per (t,h): max and sum(exp) over the 8192 entities ----------------
__global__ void __launch_bounds__(256) k2() {
    int th = blockIdx.x;                 // t*32 + h
    const float* base = g_RAW + ((size_t)(th >> 5)) * PT * NH + (th & 31);
    __shared__ float red[256];
    int tid = threadIdx.x;

    float m = -3.402823466e+38f;
    for (int n = tid; n < PT; n += 256) m = fmaxf(m, base[(size_t)n * NH]);
    red[tid] = m;
    __syncthreads();
#pragma unroll
    for (int s = 128; s; s >>= 1) {
        if (tid < s) red[tid] = fmaxf(red[tid], red[tid + s]);
        __syncthreads();
    }
    float M = red[0];
    __syncthreads();

    float su = 0.f;
    for (int n = tid; n < PT; n += 256) su += expf(base[(size_t)n * NH] - M);
    red[tid] = su;
    __syncthreads();
#pragma unroll
    for (int s = 128; s; s >>= 1) {
        if (tid < s) red[tid] += red[tid + s];
        __syncthreads();
    }
    if (tid == 0) { g_M[th] = M; g_S[th] = red[0]; }
}

// ---------------- K3: attn weights, hbar = attn^T h, o = relu(hbar@VF) + q ----------------
__global__ void __launch_bounds__(128) k3(const float* __restrict__ hist,
                                          const int* __restrict__ eidx,
                                          float* __restrict__ out) {
    __shared__ float sw[4][NH];
    __shared__ float shb[4][NU];
    int lane = threadIdx.x & 31;
    int warp = threadIdx.x >> 5;
    int t = blockIdx.y;
    int n = blockIdx.x * 4 + warp;
    int idx = eidx[t * PT + n];

    {
        float r = g_RAW[((size_t)t * PT + n) * NH + lane];
        float wv = expf(r - g_M[t * NH + lane]) / g_S[t * NH + lane];
        sw[warp][lane] = wv;
    }
    __syncwarp();

    const float4* h4 = (const float4*)(hist + (size_t)idx * NH * NU);
    float4 hb = make_float4(0.f, 0.f, 0.f, 0.f);
#pragma unroll 8
    for (int h = 0; h < NH; ++h) {
        float4 r4 = __ldcs(h4 + h * 32 + lane);
        float wh = sw[warp][h];
        hb.x = fmaf(wh, r4.x, hb.x); hb.y = fmaf(wh, r4.y, hb.y);
        hb.z = fmaf(wh, r4.z, hb.z); hb.w = fmaf(wh, r4.w, hb.w);
    }
    ((float4*)shb[warp])[lane] = hb;
    __syncwarp();

    const float4* vf4 = (const float4*)(g_VF + (size_t)t * NU * NU);
    float4 oa = make_float4(0.f, 0.f, 0.f, 0.f);
#pragma unroll 4
    for (int w = 0; w < NU; ++w) {
        float hw = shb[warp][w];
        float4 f4 = vf4[w * 32 + lane];
        oa.x = fmaf(hw, f4.x, oa.x); oa.y = fmaf(hw, f4.y, oa.y);
        oa.z = fmaf(hw, f4.z, oa.z); oa.w = fmaf(hw, f4.w, oa.w);
    }
    float4 q4 = ((const float4*)(g_Q + ((size_t)t * PT + n) * NU))[lane];
    float4 r;
    r.x = fmaxf(oa.x, 0.f) + q4.x;
    r.y = fmaxf(oa.y, 0.f) + q4.y;
    r.z = fmaxf(oa.z, 0.f) + q4.z;
    r.w = fmaxf(oa.w, 0.f) + q4.w;
    ((float4*)(out + ((size_t)t * PT + n) * NU))[lane] = r;
}

// ---------------- launch ----------------
extern "C" void kernel_launch(void* const* d_in, const int* in_sizes, int n_in,
                              void* d_out, int out_size) {
    const float* state = (const float*)d_in[0];  // (32768, 128)
    const float* hist  = (const float*)d_in[1];  // (32768, 32, 128)
    const int*   eidx  = (const int*)d_in[2];    // (4, 8192)
    const float* qw    = (const float*)d_in[3];  // (4, 128, 128)
    const float* kw    = (const float*)d_in[4];
    const float* vw    = (const float*)d_in[5];
    const float* fw    = (const float*)d_in[6];
    float* out = (float*)d_out;                  // (32768, 128)

    ktrans<<<dim3(4, 4, NT), dim3(32, 8)>>>(kw);
    kqk<<<dim3(NU, NT), NU>>>(qw);
    kvf<<<dim3(NU, NT), NU>>>(vw, fw);
    k1<<<dim3(PT / 4, NT), 128>>>(state, hist, eidx, qw);
    k2<<<NT * NH, 256>>>();
    k3<<<dim3(PT / 4, NT), 128>>>(hist, eidx, out);
}

// round 2
// speedup vs baseline: 1.2821x; 1.2821x over previous
#include <cuda_runtime.h>
#include <math.h>

#define NT 4
#define PT 8192
#define NH 32
#define NU 128

// ---------------- scratch (device globals; no allocations) ----------------
__device__ float g_KT[NT * NU * NU];          // k_w transposed per type
__device__ float g_QK[NT * NU * NU];          // q_w @ k_w^T
__device__ float g_VF[NT * NU * NU];          // v_w @ fc_w
__device__ float g_QKX[(size_t)NT * PT * NU]; // 16 MB: x @ QK per entity
__device__ float g_HB[(size_t)NT * PT * NU];  // 16 MB: attn-weighted hist
__device__ float g_RAW[(size_t)NT * PT * NH]; // 4 MB: raw attention scores
__device__ float g_M[NT * NH];
__device__ float g_S[NT * NH];

// ---------------- K0a: transpose k_w per type ----------------
__global__ void __launch_bounds__(256) ktrans(const float* __restrict__ kw) {
    __shared__ float tile[32][33];
    int t = blockIdx.z;
    int bx = blockIdx.x * 32, by = blockIdx.y * 32;
    const float* src = kw + (size_t)t * NU * NU;
    float* dst = g_KT + (size_t)t * NU * NU;
    int tx = threadIdx.x, ty = threadIdx.y;
#pragma unroll
    for (int i = 0; i < 32; i += 8)
        tile[ty + i][tx] = src[(by + ty + i) * NU + bx + tx];
    __syncthreads();
#pragma unroll
    for (int i = 0; i < 32; i += 8)
        dst[(bx + ty + i) * NU + by + tx] = tile[tx][ty + i];
}

// ---------------- K0b: QK[t][e][u] = sum_v q_w[t][e][v] * k_w[t][u][v] ----------------
__global__ void __launch_bounds__(128) kqk(const float* __restrict__ qw) {
    int t = blockIdx.y, e = blockIdx.x, u = threadIdx.x;
    const float* q = qw + ((size_t)t * NU + e) * NU;
    const float* kt = g_KT + (size_t)t * NU * NU;
    float acc = 0.f;
#pragma unroll 8
    for (int v = 0; v < NU; ++v)
        acc = fmaf(q[v], kt[v * NU + u], acc);
    g_QK[((size_t)t * NU + e) * NU + u] = acc;
}

// ---------------- K0c: VF[t][w][j] = sum_u v_w[t][w][u] * fc_w[t][u][j] ----------------
__global__ void __launch_bounds__(128) kvf(const float* __restrict__ vw,
                                           const float* __restrict__ fw) {
    int t = blockIdx.y, w = blockIdx.x, j = threadIdx.x;
    const float* vr = vw + ((size_t)t * NU + w) * NU;
    const float* f = fw + (size_t)t * NU * NU;
    float acc = 0.f;
#pragma unroll 8
    for (int u = 0; u < NU; ++u)
        acc = fmaf(vr[u], f[u * NU + j], acc);
    g_VF[((size_t)t * NU + w) * NU + j] = acc;
}

// ============ tiled GEMM: g_QKX[t][n][:] = X[eidx[t][n]][:] @ QK[t] ============
// block: 256 thr, M-tile 64 entities, N=128, K=128. dyn smem 96KB.
__global__ void __launch_bounds__(256) kgemm_qkx(const float* __restrict__ state,
                                                 const int* __restrict__ eidx) {
    extern __shared__ float smem[];
    float* sX = smem;              // [64][128]
    float4* sW4 = (float4*)(smem + 64 * NU); // [128][32] float4
    int t = blockIdx.y;
    int n0 = blockIdx.x * 64;

    const float4* w4 = (const float4*)(g_QK + (size_t)t * NU * NU);
#pragma unroll
    for (int i = threadIdx.x; i < 4096; i += 256) sW4[i] = w4[i];

    float4* sX4 = (float4*)sX;
#pragma unroll
    for (int i = threadIdx.x; i < 2048; i += 256) {
        int r = i >> 5, c = i & 31;
        int idx = eidx[t * PT + n0 + r];
        sX4[i] = __ldg((const float4*)(state + (size_t)idx * NU) + c);
    }
    __syncthreads();

    int tx = threadIdx.x & 31;   // output float4 column
    int ty = threadIdx.x >> 5;   // 8-row group
    float4 acc[8];
#pragma unroll
    for (int i = 0; i < 8; ++i) acc[i] = make_float4(0.f, 0.f, 0.f, 0.f);

#pragma unroll 4
    for (int v = 0; v < NU; ++v) {
        float4 b = sW4[v * 32 + tx];
#pragma unroll
        for (int i = 0; i < 8; ++i) {
            float a = sX[(ty * 8 + i) * NU + v];   // warp-broadcast
            acc[i].x = fmaf(a, b.x, acc[i].x);
            acc[i].y = fmaf(a, b.y, acc[i].y);
            acc[i].z = fmaf(a, b.z, acc[i].z);
            acc[i].w = fmaf(a, b.w, acc[i].w);
        }
    }
#pragma unroll
    for (int i = 0; i < 8; ++i)
        ((float4*)(g_QKX + ((size_t)t * PT + n0 + ty * 8 + i) * NU))[tx] = acc[i];
}

// ============ K1b: raw[h] = hist[idx][h][:] . qkx  (pure hist stream) ============
__global__ void __launch_bounds__(128) k1b(const float* __restrict__ hist,
                                           const int* __restrict__ eidx) {
    int lane = threadIdx.x & 31;
    int warp = threadIdx.x >> 5;
    int t = blockIdx.y;
    int n = blockIdx.x * 4 + warp;
    int idx = eidx[t * PT + n];

    float4 qkl = ((const float4*)(g_QKX + ((size_t)t * PT + n) * NU))[lane];
    const float4* h4 = (const float4*)(hist + (size_t)idx * NH * NU);
    float myraw = 0.f;
#pragma unroll 8
    for (int h = 0; h < NH; ++h) {
        float4 r4 = __ldcs(h4 + h * 32 + lane);
        float p = fmaf(r4.x, qkl.x, fmaf(r4.y, qkl.y, fmaf(r4.z, qkl.z, r4.w * qkl.w)));
#pragma unroll
        for (int o = 16; o; o >>= 1) p += __shfl_xor_sync(0xffffffffu, p, o);
        if (lane == h) myraw = p;
    }
    g_RAW[((size_t)t * PT + n) * NH + lane] = myraw;
}

// ---------------- K2: per (t,h): max and sum(exp) over 8192 entities ----------------
__global__ void __launch_bounds__(256) k2() {
    int th = blockIdx.x;
    const float* base = g_RAW + ((size_t)(th >> 5)) * PT * NH + (th & 31);
    __shared__ float red[256];
    int tid = threadIdx.x;

    float m = -3.402823466e+38f;
    for (int n = tid; n < PT; n += 256) m = fmaxf(m, base[(size_t)n * NH]);
    red[tid] = m;
    __syncthreads();
#pragma unroll
    for (int s = 128; s; s >>= 1) {
        if (tid < s) red[tid] = fmaxf(red[tid], red[tid + s]);
        __syncthreads();
    }
    float M = red[0];
    __syncthreads();

    float su = 0.f;
    for (int n = tid; n < PT; n += 256) su += expf(base[(size_t)n * NH] - M);
    red[tid] = su;
    __syncthreads();
#pragma unroll
    for (int s = 128; s; s >>= 1) {
        if (tid < s) red[tid] += red[tid + s];
        __syncthreads();
    }
    if (tid == 0) { g_M[th] = M; g_S[th] = red[0]; }
}

// ============ K3a: hbar = attn^T hist  (pure hist stream) ============
__global__ void __launch_bounds__(128) k3a(const float* __restrict__ hist,
                                           const int* __restrict__ eidx) {
    __shared__ float sw[4][NH];
    int lane = threadIdx.x & 31;
    int warp = threadIdx.x >> 5;
    int t = blockIdx.y;
    int n = blockIdx.x * 4 + warp;
    int idx = eidx[t * PT + n];

    {
        float r = g_RAW[((size_t)t * PT + n) * NH + lane];
        sw[warp][lane] = expf(r - g_M[t * NH + lane]) / g_S[t * NH + lane];
    }
    __syncwarp();

    const float4* h4 = (const float4*)(hist + (size_t)idx * NH * NU);
    float4 hb = make_float4(0.f, 0.f, 0.f, 0.f);
#pragma unroll 8
    for (int h = 0; h < NH; ++h) {
        float4 r4 = __ldcs(h4 + h * 32 + lane);
        float wh = sw[warp][h];
        hb.x = fmaf(wh, r4.x, hb.x); hb.y = fmaf(wh, r4.y, hb.y);
        hb.z = fmaf(wh, r4.z, hb.z); hb.w = fmaf(wh, r4.w, hb.w);
    }
    ((float4*)(g_HB + ((size_t)t * PT + n) * NU))[lane] = hb;
}

// ============ kout: out = relu(HB @ VF) + X @ qw   (fused double GEMM) ============
__global__ void __launch_bounds__(256) kout(const float* __restrict__ state,
                                            const int* __restrict__ eidx,
                                            const float* __restrict__ qw,
                                            float* __restrict__ out) {
    extern __shared__ float smem[];
    float* sX = smem;
    float4* sW4 = (float4*)(smem + 64 * NU);
    int t = blockIdx.y;
    int n0 = blockIdx.x * 64;
    int tx = threadIdx.x & 31;
    int ty = threadIdx.x >> 5;

    // ---- phase A: HB @ VF ----
    {
        const float4* w4 = (const float4*)(g_VF + (size_t)t * NU * NU);
#pragma unroll
        for (int i = threadIdx.x; i < 4096; i += 256) sW4[i] = w4[i];
        const float4* x4 = (const float4*)(g_HB + ((size_t)t * PT + n0) * NU);
        float4* sX4 = (float4*)sX;
#pragma unroll
        for (int i = threadIdx.x; i < 2048; i += 256) sX4[i] = x4[i];
    }
    __syncthreads();

    float4 a1[8];
#pragma unroll
    for (int i = 0; i < 8; ++i) a1[i] = make_float4(0.f, 0.f, 0.f, 0.f);
#pragma unroll 4
    for (int v = 0; v < NU; ++v) {
        float4 b = sW4[v * 32 + tx];
#pragma unroll
        for (int i = 0; i < 8; ++i) {
            float a = sX[(ty * 8 + i) * NU + v];
            a1[i].x = fmaf(a, b.x, a1[i].x);
            a1[i].y = fmaf(a, b.y, a1[i].y);
            a1[i].z = fmaf(a, b.z, a1[i].z);
            a1[i].w = fmaf(a, b.w, a1[i].w);
        }
    }
    __syncthreads();

    // ---- phase B: gathered X @ qw ----
    {
        const float4* w4 = (const float4*)(qw + (size_t)t * NU * NU);
#pragma unroll
        for (int i = threadIdx.x; i < 4096; i += 256) sW4[i] = w4[i];
        float4* sX4 = (float4*)sX;
#pragma unroll
        for (int i = threadIdx.x; i < 2048; i += 256) {
            int r = i >> 5, c = i & 31;
            int idx = eidx[t * PT + n0 + r];
            sX4[i] = __ldg((const float4*)(state + (size_t)idx * NU) + c);
        }
    }
    __syncthreads();

    float4 a2[8];
#pragma unroll
    for (int i = 0; i < 8; ++i) a2[i] = make_float4(0.f, 0.f, 0.f, 0.f);
#pragma unroll 4
    for (int v = 0; v < NU; ++v) {
        float4 b = sW4[v * 32 + tx];
#pragma unroll
        for (int i = 0; i < 8; ++i) {
            float a = sX[(ty * 8 + i) * NU + v];
            a2[i].x = fmaf(a, b.x, a2[i].x);
            a2[i].y = fmaf(a, b.y, a2[i].y);
            a2[i].z = fmaf(a, b.z, a2[i].z);
            a2[i].w = fmaf(a, b.w, a2[i].w);
        }
    }

#pragma unroll
    for (int i = 0; i < 8; ++i) {
        float4 r;
        r.x = fmaxf(a1[i].x, 0.f) + a2[i].x;
        r.y = fmaxf(a1[i].y, 0.f) + a2[i].y;
        r.z = fmaxf(a1[i].z, 0.f) + a2[i].z;
        r.w = fmaxf(a1[i].w, 0.f) + a2[i].w;
        ((float4*)(out + ((size_t)t * PT + n0 + ty * 8 + i) * NU))[tx] = r;
    }
}

// ---------------- launch ----------------
extern "C" void kernel_launch(void* const* d_in, const int* in_sizes, int n_in,
                              void* d_out, int out_size) {
    const float* state = (const float*)d_in[0];
    const float* hist  = (const float*)d_in[1];
    const int*   eidx  = (const int*)d_in[2];
    const float* qw    = (const float*)d_in[3];
    const float* kw    = (const float*)d_in[4];
    const float* vw    = (const float*)d_in[5];
    const float* fw    = (const float*)d_in[6];
    float* out = (float*)d_out;

    static bool attr_done = false;
    if (!attr_done) {
        cudaFuncSetAttribute(kgemm_qkx, cudaFuncAttributeMaxDynamicSharedMemorySize, 96 * 1024);
        cudaFuncSetAttribute(kout, cudaFuncAttributeMaxDynamicSharedMemorySize, 96 * 1024);
        attr_done = true;
    }

    ktrans<<<dim3(4, 4, NT), dim3(32, 8)>>>(kw);
    kqk<<<dim3(NU, NT), NU>>>(qw);
    kvf<<<dim3(NU, NT), NU>>>(vw, fw);
    kgemm_qkx<<<dim3(PT / 64, NT), 256, 96 * 1024>>>(state, eidx);
    k1b<<<dim3(PT / 4, NT), 128>>>(hist, eidx);
    k2<<<NT * NH, 256>>>();
    k3a<<<dim3(PT / 4, NT), 128>>>(hist, eidx);
    kout<<<dim3(PT / 64, NT), 256, 96 * 1024>>>(state, eidx, qw, out);
}